// round 4
// baseline (speedup 1.0000x reference)
#include <cuda_runtime.h>
#include <cuda_bf16.h>

// Problem shape (fixed by the dataset)
#define B_  64
#define S_  512
#define H_  768
#define L_  9
#define NT  (B_ * S_)          // 32768 destination rows
#define WPAD 10                // W row padded 9 -> 10 floats (bank-conflict-free float2 LDS)

// Scratch: dest -> source-token map (within batch row), -1 = no source (fill row)
__device__ int g_srcmap[NT];

// ---------------------------------------------------------------------------
// Kernel 1: per-batch inclusive scan of valid_mask -> dest->src map.
//   valid token s (mask=1):  dest = cum(s)-1,          src = s
//   invalid token s:         dest = count + (s - cum), src = -1
// Both cover [0,S) exactly once, so every dest slot is written.
// ---------------------------------------------------------------------------
__global__ __launch_bounds__(S_) void scan_kernel(const int* __restrict__ mask) {
    __shared__ int sh[S_];
    const int b = blockIdx.x;
    const int s = threadIdx.x;
    const int m = mask[b * S_ + s];
    sh[s] = m;
    __syncthreads();
#pragma unroll
    for (int off = 1; off < S_; off <<= 1) {
        int v = (s >= off) ? sh[s - off] : 0;
        __syncthreads();
        sh[s] += v;
        __syncthreads();
    }
    const int cum = sh[s];
    const int count = sh[S_ - 1];
    const int dest = m ? (cum - 1) : (count + (s - cum));
    g_srcmap[b * S_ + dest] = m ? s : -1;
}

// ---------------------------------------------------------------------------
// Kernel 2: fused GEMV(768x9) + bias + softmax per destination row.
// 4 lanes per token (each lane covers 192 of 768 elems), 8 tokens per warp.
// 256 threads -> 64 tokens per block -> 512 blocks.
// Because the scan compacts valid destinations to the front of each batch
// row, whole warps covering invalid dest rows skip ALL row loads and FMAs.
// ---------------------------------------------------------------------------
__global__ __launch_bounds__(256) void gemv_kernel(const float* __restrict__ seq,
                                                   const float* __restrict__ W,
                                                   const float* __restrict__ bias,
                                                   float* __restrict__ out) {
    __shared__ float Wsh[H_ * WPAD];
    __shared__ float bsh[L_];

    const int tid = threadIdx.x;
    // cooperative W load with row padding
    for (int idx = tid; idx < H_ * L_; idx += 256) {
        const int i = idx / L_;
        const int l = idx - i * L_;
        Wsh[i * WPAD + l] = W[idx];
    }
    if (tid < L_) bsh[tid] = bias[tid];
    __syncthreads();

    const int warp = tid >> 5;
    const int lane = tid & 31;
    const int grp  = lane >> 2;   // token group within warp: 0..7
    const int sub  = lane & 3;    // lane within group: 0..3

    const int t = (blockIdx.x * 8 + warp) * 8 + grp;   // destination row id
    const int bidx = t >> 9;                            // t / S_
    const int src  = g_srcmap[t];

    float acc[L_];
#pragma unroll
    for (int l = 0; l < L_; l++) acc[l] = 0.0f;

    if (src >= 0) {
        const float4* __restrict__ rp =
            reinterpret_cast<const float4*>(seq + ((size_t)(bidx << 9) + src) * H_);
        // 48 chunks of 16 floats; group of 4 lanes covers one 64B contiguous chunk
#pragma unroll 4
        for (int k = 0; k < H_ / 16; k++) {
            const float4 v = rp[4 * k + sub];
            const int ibase = 16 * k + 4 * sub;
            const float xv[4] = {v.x, v.y, v.z, v.w};
#pragma unroll
            for (int j = 0; j < 4; j++) {
                const float x = xv[j];
                const float2* __restrict__ wp =
                    reinterpret_cast<const float2*>(&Wsh[(ibase + j) * WPAD]);
                const float2 w01 = wp[0], w23 = wp[1], w45 = wp[2], w67 = wp[3];
                const float  w8  = Wsh[(ibase + j) * WPAD + 8];
                acc[0] += x * w01.x; acc[1] += x * w01.y;
                acc[2] += x * w23.x; acc[3] += x * w23.y;
                acc[4] += x * w45.x; acc[5] += x * w45.y;
                acc[6] += x * w67.x; acc[7] += x * w67.y;
                acc[8] += x * w8;
            }
        }
    }

    // reduce across the 4-lane group (butterfly -> all 4 lanes hold full sums)
#pragma unroll
    for (int l = 0; l < L_; l++) {
        acc[l] += __shfl_xor_sync(0xFFFFFFFFu, acc[l], 1);
        acc[l] += __shfl_xor_sync(0xFFFFFFFFu, acc[l], 2);
        acc[l] += bsh[l];
    }

    // softmax over 9 labels
    float mx = acc[0];
#pragma unroll
    for (int l = 1; l < L_; l++) mx = fmaxf(mx, acc[l]);
    float sum = 0.0f;
#pragma unroll
    for (int l = 0; l < L_; l++) {
        acc[l] = __expf(acc[l] - mx);
        sum += acc[l];
    }
    const float inv = 1.0f / sum;

    // split the 9 stores across the 4 group lanes (values identical per group):
    // sub 0 -> {0,4,8}, sub 1 -> {1,5}, sub 2 -> {2,6}, sub 3 -> {3,7}
    float* __restrict__ orow = out + (size_t)t * L_;
#pragma unroll
    for (int l = 0; l < L_; l++) {
        if ((l & 3) == sub) orow[l] = acc[l] * inv;
    }
}

extern "C" void kernel_launch(void* const* d_in, const int* in_sizes, int n_in,
                              void* d_out, int out_size) {
    const float* seq  = (const float*)d_in[0];  // [64,512,768] f32
    const int*   mask = (const int*)  d_in[1];  // [64,512]     i32
    const float* W    = (const float*)d_in[2];  // [768,9]      f32
    const float* bias = (const float*)d_in[3];  // [9]          f32
    float* out = (float*)d_out;                 // [64,512,9]   f32

    scan_kernel<<<B_, S_>>>(mask);
    gemv_kernel<<<NT / 64, 256>>>(seq, W, bias, out);
}